// round 15
// baseline (speedup 1.0000x reference)
#include <cuda_runtime.h>
#include <cuda_fp16.h>
#include <cstdint>

// Problem shape (fixed)
#define BB 2
#define LL 2048
#define DD 1024
#define HH 16
#define HD 64
#define MM (BB*LL)   // 4096

typedef __half fp16;

// ---------------------------------------------------------------------------
// Scratch (__device__ globals: allocation-free rule)
// ---------------------------------------------------------------------------
__device__ fp16 g_xhi[MM*DD];
__device__ fp16 g_whi[4*DD*DD];
__device__ fp16 g_qhi[MM*DD];
__device__ fp16 g_khi[MM*DD];
__device__ fp16 g_vhi[MM*DD];
__device__ fp16 g_mhi[MM*DD];

// ---------------------------------------------------------------------------
// Helpers (portable ISA only)
// ---------------------------------------------------------------------------
__device__ __forceinline__ uint32_t smem_u32(const void* p) {
    uint32_t a;
    asm("{ .reg .u64 t; cvta.to.shared.u64 t, %1; cvt.u32.u64 %0, t; }" : "=r"(a) : "l"(p));
    return a;
}
__device__ __forceinline__ void ldsm_x4(uint32_t& r0, uint32_t& r1, uint32_t& r2, uint32_t& r3,
                                        uint32_t addr) {
    asm volatile("ldmatrix.sync.aligned.m8n8.x4.shared.b16 {%0,%1,%2,%3}, [%4];"
                 : "=r"(r0), "=r"(r1), "=r"(r2), "=r"(r3) : "r"(addr));
}
__device__ __forceinline__ void ldsm_x4t(uint32_t& r0, uint32_t& r1, uint32_t& r2, uint32_t& r3,
                                         uint32_t addr) {
    asm volatile("ldmatrix.sync.aligned.m8n8.x4.trans.shared.b16 {%0,%1,%2,%3}, [%4];"
                 : "=r"(r0), "=r"(r1), "=r"(r2), "=r"(r3) : "r"(addr));
}
__device__ __forceinline__ void mma4(float* c, const uint32_t* a, const uint32_t* b) {
    asm volatile("mma.sync.aligned.m16n8k16.row.col.f32.f16.f16.f32 "
                 "{%0,%1,%2,%3}, {%4,%5,%6,%7}, {%8,%9}, {%0,%1,%2,%3};"
                 : "+f"(c[0]), "+f"(c[1]), "+f"(c[2]), "+f"(c[3])
                 : "r"(a[0]), "r"(a[1]), "r"(a[2]), "r"(a[3]), "r"(b[0]), "r"(b[1]));
}
__device__ __forceinline__ void cp16(uint32_t dst, const void* src) {
    asm volatile("cp.async.cg.shared.global [%0], [%1], 16;" :: "r"(dst), "l"(src));
}
#define CP_COMMIT() asm volatile("cp.async.commit_group;" ::: "memory")
#define CP_WAIT(N)  asm volatile("cp.async.wait_group %0;" :: "n"(N) : "memory")

// Pack (lo, hi) fp32 -> half2, then exp2 both halves in ONE f16x2 MUFU op.
__device__ __forceinline__ uint32_t h2exp2(float lo, float hi) {
    uint32_t h, r;
    asm("cvt.rn.f16x2.f32 %0, %1, %2;" : "=r"(h) : "f"(hi), "f"(lo));
    asm("ex2.approx.f16x2 %0, %1;" : "=r"(r) : "r"(h));
    return r;
}

// ---------------------------------------------------------------------------
// fp32 -> rounded fp16 conversion: x + 4 weight matrices, one launch.
// ---------------------------------------------------------------------------
__global__ __launch_bounds__(256) void split_all(const float* __restrict__ x,
                                                 const float* __restrict__ w0,
                                                 const float* __restrict__ w1,
                                                 const float* __restrict__ w2,
                                                 const float* __restrict__ w3,
                                                 fp16* __restrict__ xhi,
                                                 fp16* __restrict__ whi,
                                                 int nx4, int nw4) {
    int i = blockIdx.x * 256 + threadIdx.x;
    int z = blockIdx.y;
    const float* src;
    fp16* dst;
    int n4;
    if (z == 4) { src = x; dst = xhi; n4 = nx4; }
    else {
        src = z == 0 ? w0 : z == 1 ? w1 : z == 2 ? w2 : w3;
        dst = whi + (size_t)z * DD * DD;
        n4 = nw4;
    }
    if (i >= n4) return;
    float4 v = reinterpret_cast<const float4*>(src)[i];
    __half2* H = reinterpret_cast<__half2*>(dst);
    H[2*i]   = __floats2half2_rn(v.x, v.y);
    H[2*i+1] = __floats2half2_rn(v.z, v.w);
}

// ---------------------------------------------------------------------------
// HMMA GEMM, single-pass fp16, 4-stage cp.async pipeline (3 groups in flight
// during compute), one sync per iter.
// C = Ahi @ Whi^T + bias. CTA 128x128, BK=32, 256 threads (2x4 warps, 64x32).
// ---------------------------------------------------------------------------
#define GK 1024
#define BM 128
#define BN 128
#define BK 32
#define SZ_A (BM*80)                  // 10240 B
#define SZ_W (BN*80)                  // 10240 B
#define STG  (SZ_A + SZ_W)            // 20480 B per stage
#define NSTG 4
#define GEMM_SMEM (NSTG*STG)          // 81920 B

struct GemmTask {
    const fp16* Whi;
    const float* bias; float scale;
    float* Cf; fp16* Chi;
};

__global__ __launch_bounds__(256) void gemm_hmma(const fp16* __restrict__ Ahi,
                                                 GemmTask t0, GemmTask t1, GemmTask t2) {
    extern __shared__ __align__(16) char dsm[];
    const GemmTask tk = blockIdx.z == 0 ? t0 : blockIdx.z == 1 ? t1 : t2;
    const fp16* __restrict__ Whi = tk.Whi;

    const uint32_t sb0 = smem_u32(dsm);
    const int tid  = threadIdx.x;
    const int wid  = tid >> 5;
    const int lane = tid & 31;
    const int wm   = wid >> 2;      // 0..1 -> 64-row slab
    const int wn   = wid & 3;       // 0..3 -> 32-col slab
    const int bm   = blockIdx.y * BM;
    const int bn   = blockIdx.x * BN;

    float acc[4][4][4];
#pragma unroll
    for (int i = 0; i < 4; i++)
#pragma unroll
        for (int j = 0; j < 4; j++)
#pragma unroll
            for (int k = 0; k < 4; k++) acc[i][j][k] = 0.f;

    auto issue = [&](int stg, int k0) {
        uint32_t base = sb0 + stg * STG;
#pragma unroll
        for (int i = 0; i < 2; i++) {
            int c = tid + 256 * i;
            int r = c >> 2, q = c & 3;
            cp16(base + r * 80 + q * 16,        Ahi + (size_t)(bm + r) * GK + k0 + q * 8);
            cp16(base + SZ_A + r * 80 + q * 16, Whi + (size_t)(bn + r) * GK + k0 + q * 8);
        }
        CP_COMMIT();
    };

    const int a_r    = lane & 15;
    const int a_half = lane >> 4;
    const int b_rr   = lane & 7;
    const int b_nt   = (lane >> 4) & 1;
    const int b_kh   = (lane >> 3) & 1;

    const int NIT = GK / BK;     // 32
    issue(0, 0);
    issue(1, BK);
    issue(2, 2 * BK);
    for (int it = 0; it < NIT; it++) {
        if (it + 2 < NIT)      { CP_WAIT(2); }
        else if (it + 1 < NIT) { CP_WAIT(1); }
        else                   { CP_WAIT(0); }
        __syncthreads();
        if (it + 3 < NIT) issue((it + 3) % NSTG, (it + 3) * BK);

        const uint32_t base = sb0 + (it % NSTG) * STG;
        const uint32_t aAhi = base;
        const uint32_t aWhi = base + SZ_A;

#pragma unroll
        for (int ks = 0; ks < 2; ks++) {
            const int kk = ks * 16;
            uint32_t ah[4][4];
#pragma unroll
            for (int mt = 0; mt < 4; mt++) {
                uint32_t off = (uint32_t)(wm * 64 + mt * 16 + a_r) * 80 + (kk + a_half * 8) * 2;
                ldsm_x4(ah[mt][0], ah[mt][1], ah[mt][2], ah[mt][3], aAhi + off);
            }
            uint32_t bh[4][2];
#pragma unroll
            for (int p = 0; p < 2; p++) {
                uint32_t off = (uint32_t)(wn * 32 + p * 16 + b_nt * 8 + b_rr) * 80
                             + (kk + b_kh * 8) * 2;
                ldsm_x4(bh[p*2][0], bh[p*2][1], bh[p*2+1][0], bh[p*2+1][1], aWhi + off);
            }
#pragma unroll
            for (int mt = 0; mt < 4; mt++)
#pragma unroll
                for (int nt = 0; nt < 4; nt++)
                    mma4(acc[mt][nt], ah[mt], bh[nt]);
        }
    }

    // ---- epilogue ----
    const int gid = lane >> 2;
    const int tig = lane & 3;
#pragma unroll
    for (int mt = 0; mt < 4; mt++) {
#pragma unroll
        for (int nt = 0; nt < 4; nt++) {
            int row = bm + wm * 64 + mt * 16 + gid;
            int col = bn + wn * 32 + nt * 8 + 2 * tig;
            float b0 = tk.bias ? tk.bias[col]     : 0.f;
            float b1 = tk.bias ? tk.bias[col + 1] : 0.f;
            float v00 = (acc[mt][nt][0] + b0) * tk.scale;
            float v01 = (acc[mt][nt][1] + b1) * tk.scale;
            float v10 = (acc[mt][nt][2] + b0) * tk.scale;
            float v11 = (acc[mt][nt][3] + b1) * tk.scale;
            if (tk.Cf) {
                *reinterpret_cast<float2*>(tk.Cf + (size_t)row * GK + col)       = make_float2(v00, v01);
                *reinterpret_cast<float2*>(tk.Cf + (size_t)(row + 8) * GK + col) = make_float2(v10, v11);
            } else {
                *reinterpret_cast<__half2*>(tk.Chi + (size_t)row * GK + col) =
                    __floats2half2_rn(v00, v01);
                *reinterpret_cast<__half2*>(tk.Chi + (size_t)(row + 8) * GK + col) =
                    __floats2half2_rn(v10, v11);
            }
        }
    }
}

// ---------------------------------------------------------------------------
// HMMA flash attention, double-buffered KV, one sync per KV tile.
// Q pre-scaled by 0.125*log2(e) -> exp2-domain softmax.
// P via ex2.approx.f16x2; row sums via MMA against ones-B fragment.
// Block = 128 threads (4 warps), 64 query rows, KV tiles of 64.
// ---------------------------------------------------------------------------
#define AROWB 144                       // bytes per 64-col fp16 row
#define ATILE_B (64*AROWB)              // 9216 B per array
#define ASTG_B (2*ATILE_B)              // Kh,Vh per stage = 18432 B
#define ATTN_SMEM (2*ASTG_B)            // 36864 B

__global__ __launch_bounds__(128, 4) void attn_mma(const fp16* __restrict__ Qhi,
                                                   const fp16* __restrict__ Khi,
                                                   const fp16* __restrict__ Vhi,
                                                   fp16* __restrict__ Ohi) {
    extern __shared__ __align__(16) char asm_[];
    const uint32_t sb = smem_u32(asm_);

    const int i0 = (int)(gridDim.x - 1 - blockIdx.x) * 64;   // reversed order
    const int h  = blockIdx.y;
    const int b  = blockIdx.z;
    const int tid  = threadIdx.x;
    const int w    = tid >> 5;
    const int lane = tid & 31;
    const int gid  = lane >> 2;
    const int tig  = lane & 3;
    const int r0   = w * 16;

    const size_t baseq = ((size_t)(b * LL + i0)) * DD + h * HD;

    auto issueKV = [&](uint32_t stg, int j0) {
        const size_t basekv = ((size_t)(b * LL + j0)) * DD + h * HD;
#pragma unroll
        for (int i = 0; i < 4; i++) {
            int c = tid + 128 * i;
            int r = c >> 3, q = c & 7;
            const size_t off = basekv + (size_t)r * DD + q * 8;
            const uint32_t d = stg + r * AROWB + q * 16;
            cp16(d,           Khi + off);
            cp16(d + ATILE_B, Vhi + off);
        }
        CP_COMMIT();
    };

    // ---- stage Q through stage-1 K buffer; prefetch KV tile 0 into stage 0 ----
#pragma unroll
    for (int i = 0; i < 4; i++) {
        int c = tid + 128 * i;
        int r = c >> 3, q = c & 7;
        cp16(sb + ASTG_B + r * AROWB + q * 16, Qhi + baseq + (size_t)r * DD + q * 8);
    }
    CP_COMMIT();
    issueKV(sb, 0);
    CP_WAIT(1);
    __syncthreads();

    const int a_r = lane & 15, a_h = lane >> 4;
    uint32_t qh[4][4];
#pragma unroll
    for (int ks = 0; ks < 4; ks++) {
        uint32_t off = (uint32_t)(r0 + a_r) * AROWB + (ks * 16 + a_h * 8) * 2;
        ldsm_x4(qh[ks][0], qh[ks][1], qh[ks][2], qh[ks][3], sb + ASTG_B + off);
    }
    // first overwrite of Q buffer (KV tile 1) is issued after the t=0 barrier.

    float o[8][4];
#pragma unroll
    for (int nt = 0; nt < 8; nt++)
#pragma unroll
        for (int k = 0; k < 4; k++) o[nt][k] = 0.f;
    float mrow0 = -1e30f, mrow1 = -1e30f, lrow0 = 0.f, lrow1 = 0.f;

    const int b_rr = lane & 7;
    const int b_nt = (lane >> 4) & 1;
    const int b_kh = (lane >> 3) & 1;
    const uint32_t ones2[2] = {0x3C003C00u, 0x3C003C00u};   // half2(1,1) x2

    const int T = i0 / 64 + 1;
    for (int t = 0; t < T; t++) {
        CP_WAIT(0);
        __syncthreads();
        if (t + 1 < T) issueKV(sb + ((t + 1) & 1) * ASTG_B, (t + 1) * 64);

        const uint32_t aKh = sb + (t & 1) * ASTG_B;
        const uint32_t aVh = aKh + ATILE_B;

        // ---- S = Q K^T (exp2-domain scores) ----
        float s[8][4];
#pragma unroll
        for (int nt = 0; nt < 8; nt++)
#pragma unroll
            for (int k = 0; k < 4; k++) s[nt][k] = 0.f;

#pragma unroll
        for (int ks = 0; ks < 4; ks++) {
            const int kk = ks * 16;
            uint32_t kh[8][2];
#pragma unroll
            for (int p = 0; p < 4; p++) {
                uint32_t off = (uint32_t)(p * 16 + b_nt * 8 + b_rr) * AROWB + (kk + b_kh * 8) * 2;
                ldsm_x4(kh[p*2][0], kh[p*2][1], kh[p*2+1][0], kh[p*2+1][1], aKh + off);
            }
#pragma unroll
            for (int nt = 0; nt < 8; nt++)
                mma4(s[nt], qh[ks], kh[nt]);
        }

        // ---- causal mask (diagonal tile only) ----
        if (t == T - 1) {
#pragma unroll
            for (int nt = 0; nt < 8; nt++) {
                int col0 = nt * 8 + 2 * tig;
                int rowa = r0 + gid, rowb = rowa + 8;
                if (col0     > rowa) s[nt][0] = -1e30f;
                if (col0 + 1 > rowa) s[nt][1] = -1e30f;
                if (col0     > rowb) s[nt][2] = -1e30f;
                if (col0 + 1 > rowb) s[nt][3] = -1e30f;
            }
        }

        // ---- online softmax: max (shuffles), P via f16x2 ex2 ----
        float mxa = -1e30f, mxb = -1e30f;
#pragma unroll
        for (int nt = 0; nt < 8; nt++) {
            mxa = fmaxf(mxa, fmaxf(s[nt][0], s[nt][1]));
            mxb = fmaxf(mxb, fmaxf(s[nt][2], s[nt][3]));
        }
        mxa = fmaxf(mxa, __shfl_xor_sync(0xFFFFFFFFu, mxa, 1));
        mxa = fmaxf(mxa, __shfl_xor_sync(0xFFFFFFFFu, mxa, 2));
        mxb = fmaxf(mxb, __shfl_xor_sync(0xFFFFFFFFu, mxb, 1));
        mxb = fmaxf(mxb, __shfl_xor_sync(0xFFFFFFFFu, mxb, 2));

        float mna = fmaxf(mrow0, mxa), mnb = fmaxf(mrow1, mxb);
        float ala = exp2f(mrow0 - mna), alb = exp2f(mrow1 - mnb);

        uint32_t ph[4][4];
#pragma unroll
        for (int ks2 = 0; ks2 < 4; ks2++) {
            const float* sa  = s[2*ks2];
            const float* sb2 = s[2*ks2 + 1];
            ph[ks2][0] = h2exp2(sa[0]  - mna, sa[1]  - mna);
            ph[ks2][1] = h2exp2(sa[2]  - mnb, sa[3]  - mnb);
            ph[ks2][2] = h2exp2(sb2[0] - mna, sb2[1] - mna);
            ph[ks2][3] = h2exp2(sb2[2] - mnb, sb2[3] - mnb);
        }

        // ---- row sums via MMA with ones-B ----
        float asum[4] = {0.f, 0.f, 0.f, 0.f};
#pragma unroll
        for (int ks2 = 0; ks2 < 4; ks2++)
            mma4(asum, ph[ks2], ones2);
        lrow0 = lrow0 * ala + asum[0]; mrow0 = mna;
        lrow1 = lrow1 * alb + asum[2]; mrow1 = mnb;

#pragma unroll
        for (int nt = 0; nt < 8; nt++) {
            o[nt][0] *= ala; o[nt][1] *= ala;
            o[nt][2] *= alb; o[nt][3] *= alb;
        }

        // ---- O += P V ----
#pragma unroll
        for (int ks2 = 0; ks2 < 4; ks2++) {
            uint32_t vh[8][2];
#pragma unroll
            for (int p = 0; p < 4; p++) {
                uint32_t off = (uint32_t)(ks2 * 16 + b_kh * 8 + b_rr) * AROWB
                             + (p * 16 + b_nt * 8) * 2;
                ldsm_x4t(vh[p*2][0], vh[p*2][1], vh[p*2+1][0], vh[p*2+1][1], aVh + off);
            }
#pragma unroll
            for (int nt = 0; nt < 8; nt++)
                mma4(o[nt], ph[ks2], vh[nt]);
        }
    }

    // ---- epilogue: normalize, round to fp16, store ----
    const float inv0 = 1.0f / lrow0;
    const float inv1 = 1.0f / lrow1;
    const size_t rowa = (size_t)(b * LL + i0 + r0 + gid) * DD + h * HD;
    const size_t rowb = rowa + (size_t)8 * DD;
#pragma unroll
    for (int nt = 0; nt < 8; nt++) {
        int col = nt * 8 + 2 * tig;
        *reinterpret_cast<__half2*>(Ohi + rowa + col) =
            __floats2half2_rn(o[nt][0] * inv0, o[nt][1] * inv0);
        *reinterpret_cast<__half2*>(Ohi + rowb + col) =
            __floats2half2_rn(o[nt][2] * inv1, o[nt][3] * inv1);
    }
}

// ---------------------------------------------------------------------------
extern "C" void kernel_launch(void* const* d_in, const int* in_sizes, int n_in,
                              void* d_out, int out_size) {
    const float* x  = (const float*)d_in[0];
    const float* WQ = (const float*)d_in[1];
    const float* bQ = (const float*)d_in[2];
    const float* WK = (const float*)d_in[3];
    const float* bK = (const float*)d_in[4];
    const float* WV = (const float*)d_in[5];
    const float* bV = (const float*)d_in[6];
    const float* Wc = (const float*)d_in[7];
    float* out = (float*)d_out;

    cudaFuncSetAttribute(gemm_hmma, cudaFuncAttributeMaxDynamicSharedMemorySize, GEMM_SMEM);
    cudaFuncSetAttribute(attn_mma,  cudaFuncAttributeMaxDynamicSharedMemorySize, ATTN_SMEM);

    fp16 *xhi, *whi, *qhi, *khi, *vhi, *mhi;
    cudaGetSymbolAddress((void**)&xhi, g_xhi);
    cudaGetSymbolAddress((void**)&whi, g_whi);
    cudaGetSymbolAddress((void**)&qhi, g_qhi);
    cudaGetSymbolAddress((void**)&khi, g_khi);
    cudaGetSymbolAddress((void**)&vhi, g_vhi);
    cudaGetSymbolAddress((void**)&mhi, g_mhi);

    const int nx4 = MM * DD / 4;     // 1048576
    const int nw4 = DD * DD / 4;     // 262144

    dim3 gs((nx4 + 255) / 256, 5);   // y=0..3 weights, y=4 x
    split_all<<<gs, 256>>>(x, WQ, WK, WV, Wc, xhi, whi, nx4, nw4);

    // Q scale folds in log2(e): attention softmax runs in exp2 domain.
    const float QSCALE = 0.125f * 1.4426950408889634f;
    GemmTask tq = {whi + 0*DD*DD, bQ, QSCALE, nullptr, qhi};
    GemmTask tk = {whi + 1*DD*DD, bK, 1.0f,   nullptr, khi};
    GemmTask tv = {whi + 2*DD*DD, bV, 1.0f,   nullptr, vhi};
    dim3 gqkv(DD / BN, MM / BM, 3);    // (8, 32, 3) = 768 CTAs
    gemm_hmma<<<gqkv, 256, GEMM_SMEM>>>(xhi, tq, tk, tv);

    dim3 ga(LL / 64, HH, BB);          // (32, 16, 2)
    attn_mma<<<ga, 128, ATTN_SMEM>>>(qhi, khi, vhi, mhi);

    GemmTask tc = {whi + 3*DD*DD, nullptr, 1.0f, out, nullptr};
    dim3 go(DD / BN, MM / BM, 1);      // (8, 32, 1)
    gemm_hmma<<<go, 256, GEMM_SMEM>>>(mhi, tc, tc, tc);
}

// round 16
// speedup vs baseline: 1.5365x; 1.5365x over previous
#include <cuda_runtime.h>
#include <cuda_fp16.h>
#include <cstdint>

// Problem shape (fixed)
#define BB 2
#define LL 2048
#define DD 1024
#define HH 16
#define HD 64
#define MM (BB*LL)   // 4096

typedef __half fp16;

// ---------------------------------------------------------------------------
// Scratch (__device__ globals: allocation-free rule)
// ---------------------------------------------------------------------------
__device__ fp16 g_xhi[MM*DD];
__device__ fp16 g_whi[4*DD*DD];
__device__ fp16 g_qhi[MM*DD];
__device__ fp16 g_khi[MM*DD];
__device__ fp16 g_vhi[MM*DD];
__device__ fp16 g_mhi[MM*DD];

// ---------------------------------------------------------------------------
// Helpers (portable ISA only)
// ---------------------------------------------------------------------------
__device__ __forceinline__ uint32_t smem_u32(const void* p) {
    uint32_t a;
    asm("{ .reg .u64 t; cvta.to.shared.u64 t, %1; cvt.u32.u64 %0, t; }" : "=r"(a) : "l"(p));
    return a;
}
__device__ __forceinline__ void ldsm_x4(uint32_t& r0, uint32_t& r1, uint32_t& r2, uint32_t& r3,
                                        uint32_t addr) {
    asm volatile("ldmatrix.sync.aligned.m8n8.x4.shared.b16 {%0,%1,%2,%3}, [%4];"
                 : "=r"(r0), "=r"(r1), "=r"(r2), "=r"(r3) : "r"(addr));
}
__device__ __forceinline__ void ldsm_x4t(uint32_t& r0, uint32_t& r1, uint32_t& r2, uint32_t& r3,
                                         uint32_t addr) {
    asm volatile("ldmatrix.sync.aligned.m8n8.x4.trans.shared.b16 {%0,%1,%2,%3}, [%4];"
                 : "=r"(r0), "=r"(r1), "=r"(r2), "=r"(r3) : "r"(addr));
}
__device__ __forceinline__ void mma4(float* c, const uint32_t* a, const uint32_t* b) {
    asm volatile("mma.sync.aligned.m16n8k16.row.col.f32.f16.f16.f32 "
                 "{%0,%1,%2,%3}, {%4,%5,%6,%7}, {%8,%9}, {%0,%1,%2,%3};"
                 : "+f"(c[0]), "+f"(c[1]), "+f"(c[2]), "+f"(c[3])
                 : "r"(a[0]), "r"(a[1]), "r"(a[2]), "r"(a[3]), "r"(b[0]), "r"(b[1]));
}
__device__ __forceinline__ void cp16(uint32_t dst, const void* src) {
    asm volatile("cp.async.cg.shared.global [%0], [%1], 16;" :: "r"(dst), "l"(src));
}
#define CP_COMMIT() asm volatile("cp.async.commit_group;" ::: "memory")
#define CP_WAIT(N)  asm volatile("cp.async.wait_group %0;" :: "n"(N) : "memory")

// Pack (lo, hi) fp32 -> half2, then exp2 both halves in ONE f16x2 MUFU op.
// P is consumed in fp16 anyway, so the approx f16 ex2 loses nothing.
__device__ __forceinline__ uint32_t h2exp2(float lo, float hi) {
    uint32_t h, r;
    asm("cvt.rn.f16x2.f32 %0, %1, %2;" : "=r"(h) : "f"(hi), "f"(lo));
    asm("ex2.approx.f16x2 %0, %1;" : "=r"(r) : "r"(h));
    return r;
}

// ---------------------------------------------------------------------------
// fp32 -> rounded fp16 conversion: x + 4 weight matrices, one launch.
// ---------------------------------------------------------------------------
__global__ __launch_bounds__(256) void split_all(const float* __restrict__ x,
                                                 const float* __restrict__ w0,
                                                 const float* __restrict__ w1,
                                                 const float* __restrict__ w2,
                                                 const float* __restrict__ w3,
                                                 fp16* __restrict__ xhi,
                                                 fp16* __restrict__ whi,
                                                 int nx4, int nw4) {
    int i = blockIdx.x * 256 + threadIdx.x;
    int z = blockIdx.y;
    const float* src;
    fp16* dst;
    int n4;
    if (z == 4) { src = x; dst = xhi; n4 = nx4; }
    else {
        src = z == 0 ? w0 : z == 1 ? w1 : z == 2 ? w2 : w3;
        dst = whi + (size_t)z * DD * DD;
        n4 = nw4;
    }
    if (i >= n4) return;
    float4 v = reinterpret_cast<const float4*>(src)[i];
    __half2* H = reinterpret_cast<__half2*>(dst);
    H[2*i]   = __floats2half2_rn(v.x, v.y);
    H[2*i+1] = __floats2half2_rn(v.z, v.w);
}

// ---------------------------------------------------------------------------
// HMMA GEMM, single-pass fp16, 3-stage cp.async pipeline, one sync per iter.
// C = Ahi @ Whi^T + bias. CTA 128x128, BK=32, 256 threads (2x4 warps, 64x32).
// (3 stages / 61 KB is the measured optimum: 4 stages / 82 KB regressed by
//  cutting CTA residency; 64-wide tiles regressed on L2 traffic.)
// ---------------------------------------------------------------------------
#define GK 1024
#define BM 128
#define BN 128
#define BK 32
#define SZ_A (BM*80)                  // 10240 B
#define SZ_W (BN*80)                  // 10240 B
#define STG  (SZ_A + SZ_W)            // 20480 B per stage
#define GEMM_SMEM (3*STG)             // 61440 B

struct GemmTask {
    const fp16* Whi;
    const float* bias; float scale;
    float* Cf; fp16* Chi;
};

__global__ __launch_bounds__(256) void gemm_hmma(const fp16* __restrict__ Ahi,
                                                 GemmTask t0, GemmTask t1, GemmTask t2) {
    extern __shared__ __align__(16) char dsm[];
    const GemmTask tk = blockIdx.z == 0 ? t0 : blockIdx.z == 1 ? t1 : t2;
    const fp16* __restrict__ Whi = tk.Whi;

    const uint32_t sb0 = smem_u32(dsm);
    const int tid  = threadIdx.x;
    const int wid  = tid >> 5;
    const int lane = tid & 31;
    const int wm   = wid >> 2;      // 0..1 -> 64-row slab
    const int wn   = wid & 3;       // 0..3 -> 32-col slab
    const int bm   = blockIdx.y * BM;
    const int bn   = blockIdx.x * BN;

    float acc[4][4][4];
#pragma unroll
    for (int i = 0; i < 4; i++)
#pragma unroll
        for (int j = 0; j < 4; j++)
#pragma unroll
            for (int k = 0; k < 4; k++) acc[i][j][k] = 0.f;

    auto issue = [&](int stg, int k0) {
        uint32_t base = sb0 + stg * STG;
#pragma unroll
        for (int i = 0; i < 2; i++) {
            int c = tid + 256 * i;
            int r = c >> 2, q = c & 3;
            cp16(base + r * 80 + q * 16,        Ahi + (size_t)(bm + r) * GK + k0 + q * 8);
            cp16(base + SZ_A + r * 80 + q * 16, Whi + (size_t)(bn + r) * GK + k0 + q * 8);
        }
        CP_COMMIT();
    };

    const int a_r    = lane & 15;
    const int a_half = lane >> 4;
    const int b_rr   = lane & 7;
    const int b_nt   = (lane >> 4) & 1;
    const int b_kh   = (lane >> 3) & 1;

    const int NIT = GK / BK;     // 32
    issue(0, 0);
    issue(1, BK);
    for (int it = 0; it < NIT; it++) {
        if (it + 1 < NIT) { CP_WAIT(1); } else { CP_WAIT(0); }
        __syncthreads();
        if (it + 2 < NIT) issue((it + 2) % 3, (it + 2) * BK);

        const uint32_t base = sb0 + (it % 3) * STG;
        const uint32_t aAhi = base;
        const uint32_t aWhi = base + SZ_A;

#pragma unroll
        for (int ks = 0; ks < 2; ks++) {
            const int kk = ks * 16;
            uint32_t ah[4][4];
#pragma unroll
            for (int mt = 0; mt < 4; mt++) {
                uint32_t off = (uint32_t)(wm * 64 + mt * 16 + a_r) * 80 + (kk + a_half * 8) * 2;
                ldsm_x4(ah[mt][0], ah[mt][1], ah[mt][2], ah[mt][3], aAhi + off);
            }
            uint32_t bh[4][2];
#pragma unroll
            for (int p = 0; p < 2; p++) {
                uint32_t off = (uint32_t)(wn * 32 + p * 16 + b_nt * 8 + b_rr) * 80
                             + (kk + b_kh * 8) * 2;
                ldsm_x4(bh[p*2][0], bh[p*2][1], bh[p*2+1][0], bh[p*2+1][1], aWhi + off);
            }
#pragma unroll
            for (int mt = 0; mt < 4; mt++)
#pragma unroll
                for (int nt = 0; nt < 4; nt++)
                    mma4(acc[mt][nt], ah[mt], bh[nt]);
        }
    }

    // ---- epilogue ----
    const int gid = lane >> 2;
    const int tig = lane & 3;
#pragma unroll
    for (int mt = 0; mt < 4; mt++) {
#pragma unroll
        for (int nt = 0; nt < 4; nt++) {
            int row = bm + wm * 64 + mt * 16 + gid;
            int col = bn + wn * 32 + nt * 8 + 2 * tig;
            float b0 = tk.bias ? tk.bias[col]     : 0.f;
            float b1 = tk.bias ? tk.bias[col + 1] : 0.f;
            float v00 = (acc[mt][nt][0] + b0) * tk.scale;
            float v01 = (acc[mt][nt][1] + b1) * tk.scale;
            float v10 = (acc[mt][nt][2] + b0) * tk.scale;
            float v11 = (acc[mt][nt][3] + b1) * tk.scale;
            if (tk.Cf) {
                *reinterpret_cast<float2*>(tk.Cf + (size_t)row * GK + col)       = make_float2(v00, v01);
                *reinterpret_cast<float2*>(tk.Cf + (size_t)(row + 8) * GK + col) = make_float2(v10, v11);
            } else {
                *reinterpret_cast<__half2*>(tk.Chi + (size_t)row * GK + col) =
                    __floats2half2_rn(v00, v01);
                *reinterpret_cast<__half2*>(tk.Chi + (size_t)(row + 8) * GK + col) =
                    __floats2half2_rn(v10, v11);
            }
        }
    }
}

// ---------------------------------------------------------------------------
// HMMA flash attention, double-buffered KV, one sync per KV tile.
// Q pre-scaled by 0.125*log2(e) -> exp2-domain softmax.
// P computed with ex2.approx.f16x2 (P is fp16 anyway); row sums via an
// extra MMA against a ones-B fragment (no shuffles, exact fp32 accumulate).
// Block = 128 threads (4 warps), 64 query rows, KV tiles of 64.
// ---------------------------------------------------------------------------
#define AROWB 144                       // bytes per 64-col fp16 row
#define ATILE_B (64*AROWB)              // 9216 B per array
#define ASTG_B (2*ATILE_B)              // Kh,Vh per stage = 18432 B
#define ATTN_SMEM (2*ASTG_B)            // 36864 B

__global__ __launch_bounds__(128, 4) void attn_mma(const fp16* __restrict__ Qhi,
                                                   const fp16* __restrict__ Khi,
                                                   const fp16* __restrict__ Vhi,
                                                   fp16* __restrict__ Ohi) {
    extern __shared__ __align__(16) char asm_[];
    const uint32_t sb = smem_u32(asm_);

    const int i0 = (int)(gridDim.x - 1 - blockIdx.x) * 64;   // reversed order
    const int h  = blockIdx.y;
    const int b  = blockIdx.z;
    const int tid  = threadIdx.x;
    const int w    = tid >> 5;
    const int lane = tid & 31;
    const int gid  = lane >> 2;
    const int tig  = lane & 3;
    const int r0   = w * 16;

    const size_t baseq = ((size_t)(b * LL + i0)) * DD + h * HD;

    auto issueKV = [&](uint32_t stg, int j0) {
        const size_t basekv = ((size_t)(b * LL + j0)) * DD + h * HD;
#pragma unroll
        for (int i = 0; i < 4; i++) {
            int c = tid + 128 * i;
            int r = c >> 3, q = c & 7;
            const size_t off = basekv + (size_t)r * DD + q * 8;
            const uint32_t d = stg + r * AROWB + q * 16;
            cp16(d,           Khi + off);
            cp16(d + ATILE_B, Vhi + off);
        }
        CP_COMMIT();
    };

    // ---- stage Q through stage-1 K buffer; prefetch KV tile 0 into stage 0 ----
#pragma unroll
    for (int i = 0; i < 4; i++) {
        int c = tid + 128 * i;
        int r = c >> 3, q = c & 7;
        cp16(sb + ASTG_B + r * AROWB + q * 16, Qhi + baseq + (size_t)r * DD + q * 8);
    }
    CP_COMMIT();
    issueKV(sb, 0);
    CP_WAIT(1);
    __syncthreads();

    const int a_r = lane & 15, a_h = lane >> 4;
    uint32_t qh[4][4];
#pragma unroll
    for (int ks = 0; ks < 4; ks++) {
        uint32_t off = (uint32_t)(r0 + a_r) * AROWB + (ks * 16 + a_h * 8) * 2;
        ldsm_x4(qh[ks][0], qh[ks][1], qh[ks][2], qh[ks][3], sb + ASTG_B + off);
    }
    // first overwrite of Q buffer (KV tile 1) is issued after the t=0 barrier.

    float o[8][4];
#pragma unroll
    for (int nt = 0; nt < 8; nt++)
#pragma unroll
        for (int k = 0; k < 4; k++) o[nt][k] = 0.f;
    float mrow0 = -1e30f, mrow1 = -1e30f, lrow0 = 0.f, lrow1 = 0.f;

    const int b_rr = lane & 7;
    const int b_nt = (lane >> 4) & 1;
    const int b_kh = (lane >> 3) & 1;
    const uint32_t ones2[2] = {0x3C003C00u, 0x3C003C00u};   // half2(1,1) x2

    const int T = i0 / 64 + 1;
    for (int t = 0; t < T; t++) {
        CP_WAIT(0);
        __syncthreads();
        if (t + 1 < T) issueKV(sb + ((t + 1) & 1) * ASTG_B, (t + 1) * 64);

        const uint32_t aKh = sb + (t & 1) * ASTG_B;
        const uint32_t aVh = aKh + ATILE_B;

        // ---- S = Q K^T (exp2-domain scores) ----
        float s[8][4];
#pragma unroll
        for (int nt = 0; nt < 8; nt++)
#pragma unroll
            for (int k = 0; k < 4; k++) s[nt][k] = 0.f;

#pragma unroll
        for (int ks = 0; ks < 4; ks++) {
            const int kk = ks * 16;
            uint32_t kh[8][2];
#pragma unroll
            for (int p = 0; p < 4; p++) {
                uint32_t off = (uint32_t)(p * 16 + b_nt * 8 + b_rr) * AROWB + (kk + b_kh * 8) * 2;
                ldsm_x4(kh[p*2][0], kh[p*2][1], kh[p*2+1][0], kh[p*2+1][1], aKh + off);
            }
#pragma unroll
            for (int nt = 0; nt < 8; nt++)
                mma4(s[nt], qh[ks], kh[nt]);
        }

        // ---- causal mask (diagonal tile only) ----
        if (t == T - 1) {
#pragma unroll
            for (int nt = 0; nt < 8; nt++) {
                int col0 = nt * 8 + 2 * tig;
                int rowa = r0 + gid, rowb = rowa + 8;
                if (col0     > rowa) s[nt][0] = -1e30f;
                if (col0 + 1 > rowa) s[nt][1] = -1e30f;
                if (col0     > rowb) s[nt][2] = -1e30f;
                if (col0 + 1 > rowb) s[nt][3] = -1e30f;
            }
        }

        // ---- online softmax: max (shuffles), P via f16x2 ex2 ----
        float mxa = -1e30f, mxb = -1e30f;
#pragma unroll
        for (int nt = 0; nt < 8; nt++) {
            mxa = fmaxf(mxa, fmaxf(s[nt][0], s[nt][1]));
            mxb = fmaxf(mxb, fmaxf(s[nt][2], s[nt][3]));
        }
        mxa = fmaxf(mxa, __shfl_xor_sync(0xFFFFFFFFu, mxa, 1));
        mxa = fmaxf(mxa, __shfl_xor_sync(0xFFFFFFFFu, mxa, 2));
        mxb = fmaxf(mxb, __shfl_xor_sync(0xFFFFFFFFu, mxb, 1));
        mxb = fmaxf(mxb, __shfl_xor_sync(0xFFFFFFFFu, mxb, 2));

        float mna = fmaxf(mrow0, mxa), mnb = fmaxf(mrow1, mxb);
        float ala = exp2f(mrow0 - mna), alb = exp2f(mrow1 - mnb);

        uint32_t ph[4][4];
#pragma unroll
        for (int ks2 = 0; ks2 < 4; ks2++) {
            const float* sa  = s[2*ks2];
            const float* sb2 = s[2*ks2 + 1];
            ph[ks2][0] = h2exp2(sa[0]  - mna, sa[1]  - mna);
            ph[ks2][1] = h2exp2(sa[2]  - mnb, sa[3]  - mnb);
            ph[ks2][2] = h2exp2(sb2[0] - mna, sb2[1] - mna);
            ph[ks2][3] = h2exp2(sb2[2] - mnb, sb2[3] - mnb);
        }

        // ---- row sums via MMA with ones-B ----
        float asum[4] = {0.f, 0.f, 0.f, 0.f};
#pragma unroll
        for (int ks2 = 0; ks2 < 4; ks2++)
            mma4(asum, ph[ks2], ones2);
        lrow0 = lrow0 * ala + asum[0]; mrow0 = mna;
        lrow1 = lrow1 * alb + asum[2]; mrow1 = mnb;

#pragma unroll
        for (int nt = 0; nt < 8; nt++) {
            o[nt][0] *= ala; o[nt][1] *= ala;
            o[nt][2] *= alb; o[nt][3] *= alb;
        }

        // ---- O += P V ----
#pragma unroll
        for (int ks2 = 0; ks2 < 4; ks2++) {
            uint32_t vh[8][2];
#pragma unroll
            for (int p = 0; p < 4; p++) {
                uint32_t off = (uint32_t)(ks2 * 16 + b_kh * 8 + b_rr) * AROWB
                             + (p * 16 + b_nt * 8) * 2;
                ldsm_x4t(vh[p*2][0], vh[p*2][1], vh[p*2+1][0], vh[p*2+1][1], aVh + off);
            }
#pragma unroll
            for (int nt = 0; nt < 8; nt++)
                mma4(o[nt], ph[ks2], vh[nt]);
        }
    }

    // ---- epilogue: normalize, round to fp16, store ----
    const float inv0 = 1.0f / lrow0;
    const float inv1 = 1.0f / lrow1;
    const size_t rowa = (size_t)(b * LL + i0 + r0 + gid) * DD + h * HD;
    const size_t rowb = rowa + (size_t)8 * DD;
#pragma unroll
    for (int nt = 0; nt < 8; nt++) {
        int col = nt * 8 + 2 * tig;
        *reinterpret_cast<__half2*>(Ohi + rowa + col) =
            __floats2half2_rn(o[nt][0] * inv0, o[nt][1] * inv0);
        *reinterpret_cast<__half2*>(Ohi + rowb + col) =
            __floats2half2_rn(o[nt][2] * inv1, o[nt][3] * inv1);
    }
}

// ---------------------------------------------------------------------------
extern "C" void kernel_launch(void* const* d_in, const int* in_sizes, int n_in,
                              void* d_out, int out_size) {
    const float* x  = (const float*)d_in[0];
    const float* WQ = (const float*)d_in[1];
    const float* bQ = (const float*)d_in[2];
    const float* WK = (const float*)d_in[3];
    const float* bK = (const float*)d_in[4];
    const float* WV = (const float*)d_in[5];
    const float* bV = (const float*)d_in[6];
    const float* Wc = (const float*)d_in[7];
    float* out = (float*)d_out;

    cudaFuncSetAttribute(gemm_hmma, cudaFuncAttributeMaxDynamicSharedMemorySize, GEMM_SMEM);
    cudaFuncSetAttribute(attn_mma,  cudaFuncAttributeMaxDynamicSharedMemorySize, ATTN_SMEM);

    fp16 *xhi, *whi, *qhi, *khi, *vhi, *mhi;
    cudaGetSymbolAddress((void**)&xhi, g_xhi);
    cudaGetSymbolAddress((void**)&whi, g_whi);
    cudaGetSymbolAddress((void**)&qhi, g_qhi);
    cudaGetSymbolAddress((void**)&khi, g_khi);
    cudaGetSymbolAddress((void**)&vhi, g_vhi);
    cudaGetSymbolAddress((void**)&mhi, g_mhi);

    const int nx4 = MM * DD / 4;     // 1048576
    const int nw4 = DD * DD / 4;     // 262144

    dim3 gs((nx4 + 255) / 256, 5);   // y=0..3 weights, y=4 x
    split_all<<<gs, 256>>>(x, WQ, WK, WV, Wc, xhi, whi, nx4, nw4);

    // Q scale folds in log2(e): attention softmax runs in exp2 domain.
    const float QSCALE = 0.125f * 1.4426950408889634f;
    GemmTask tq = {whi + 0*DD*DD, bQ, QSCALE, nullptr, qhi};
    GemmTask tk = {whi + 1*DD*DD, bK, 1.0f,   nullptr, khi};
    GemmTask tv = {whi + 2*DD*DD, bV, 1.0f,   nullptr, vhi};
    dim3 gqkv(DD / BN, MM / BM, 3);    // (8, 32, 3) = 768 CTAs
    gemm_hmma<<<gqkv, 256, GEMM_SMEM>>>(xhi, tq, tk, tv);

    dim3 ga(LL / 64, HH, BB);          // (32, 16, 2)
    attn_mma<<<ga, 128, ATTN_SMEM>>>(qhi, khi, vhi, mhi);

    GemmTask tc = {whi + 3*DD*DD, nullptr, 1.0f, out, nullptr};
    dim3 go(DD / BN, MM / BM, 1);      // (8, 32, 1)
    gemm_hmma<<<go, 256, GEMM_SMEM>>>(mhi, tc, tc, tc);
}